// round 3
// baseline (speedup 1.0000x reference)
#include <cuda_runtime.h>

// ---------------------------------------------------------------------------
// Compile-time Cayley sign for Cl(p=3, q=1, r=0): 16 blades.
// e_i * e_j = sign(i,j) * e_{i XOR j}
// sign = (-1)^{# pairs (p in i, q in j) with p > q}  *  metric factor,
// where metric = (+1,+1,+1,-1): generator 3 (bit 3) squares to -1.
// Equivalent to the reference's insertion-sort construction for a diagonal
// metric.
// ---------------------------------------------------------------------------

__host__ __device__ constexpr int ct_popc(unsigned x) {
    int c = 0;
    while (x) { c += (int)(x & 1u); x >>= 1; }
    return c;
}

__host__ __device__ constexpr float ct_sign(int i, int j) {
    // count pairs (p in i, q in j) with p > q
    int swaps = 0;
    unsigned a = ((unsigned)i) >> 1;
    while (a) { swaps += ct_popc(a & (unsigned)j); a >>= 1; }
    float s = (swaps & 1) ? -1.0f : 1.0f;
    // metric: generators 0..2 -> +1, generator 3 -> -1
    if ((i & j) & 0x8) s = -s;
    return s;
}

// ---------------------------------------------------------------------------
// Kernel: one thread per multivector pair (row).
// Loads 16 floats of a and b as 4x float4, does 256 compile-time-signed FMAs
// into 16 accumulators (c = i ^ j), applies nan_to_num + clip, stores 4x float4.
// ---------------------------------------------------------------------------

__global__ void __launch_bounds__(256)
clifford_gp_kernel(const float4* __restrict__ a4,
                   const float4* __restrict__ b4,
                   float4* __restrict__ o4,
                   int n_rows) {
    int t = blockIdx.x * blockDim.x + threadIdx.x;
    if (t >= n_rows) return;

    float4 av[4], bv[4];
#pragma unroll
    for (int k = 0; k < 4; k++) {
        av[k] = a4[t * 4 + k];
        bv[k] = b4[t * 4 + k];
    }

    float A[16], B[16];
#pragma unroll
    for (int k = 0; k < 4; k++) {
        A[4 * k + 0] = av[k].x; A[4 * k + 1] = av[k].y;
        A[4 * k + 2] = av[k].z; A[4 * k + 3] = av[k].w;
        B[4 * k + 0] = bv[k].x; B[4 * k + 1] = bv[k].y;
        B[4 * k + 2] = bv[k].z; B[4 * k + 3] = bv[k].w;
    }

    float O[16];
#pragma unroll
    for (int c = 0; c < 16; c++) O[c] = 0.0f;

#pragma unroll
    for (int i = 0; i < 16; i++) {
#pragma unroll
        for (int j = 0; j < 16; j++) {
            // ct_sign(i, j) constant-folds post-unroll to +-1; the multiply
            // folds into the FFMA's operand-negation modifier.
            O[i ^ j] = fmaf(ct_sign(i, j) * A[i], B[j], O[i ^ j]);
        }
    }

    // nan -> 0, then clip to [-1000, 1000] (covers the +-10000 inf mapping)
#pragma unroll
    for (int c = 0; c < 16; c++) {
        float v = O[c];
        if (v != v) v = 0.0f;
        v = fminf(fmaxf(v, -1000.0f), 1000.0f);
        O[c] = v;
    }

    float4 ov[4];
#pragma unroll
    for (int k = 0; k < 4; k++) {
        ov[k].x = O[4 * k + 0]; ov[k].y = O[4 * k + 1];
        ov[k].z = O[4 * k + 2]; ov[k].w = O[4 * k + 3];
        o4[t * 4 + k] = ov[k];
    }
}

extern "C" void kernel_launch(void* const* d_in, const int* in_sizes, int n_in,
                              void* d_out, int out_size) {
    const float4* a4 = (const float4*)d_in[0];
    const float4* b4 = (const float4*)d_in[1];
    float4* o4 = (float4*)d_out;

    int n_rows = in_sizes[0] / 16;
    int threads = 256;
    int blocks = (n_rows + threads - 1) / threads;
    clifford_gp_kernel<<<blocks, threads>>>(a4, b4, o4, n_rows);
}

// round 6
// speedup vs baseline: 3.6000x; 3.6000x over previous
#include <cuda_runtime.h>

// ---------------------------------------------------------------------------
// Compile-time Cayley sign for Cl(p=3, q=1, r=0): 16 blades.
// e_i * e_j = sign(i,j) * e_{i XOR j}
// sign = (-1)^{# pairs (p in i, q in j) with p > q} * metric factor,
// metric = (+1,+1,+1,-1): generator 3 (bit 3) squares to -1.
// ---------------------------------------------------------------------------

__host__ __device__ constexpr int ct_popc(unsigned x) {
    int c = 0;
    while (x) { c += (int)(x & 1u); x >>= 1; }
    return c;
}

__host__ __device__ constexpr float ct_sign(int i, int j) {
    int swaps = 0;
    unsigned a = ((unsigned)i) >> 1;
    while (a) { swaps += ct_popc(a & (unsigned)j); a >>= 1; }
    float s = (swaps & 1) ? -1.0f : 1.0f;
    if ((i & j) & 0x8) s = -s;   // e3^2 = -1
    return s;
}

// ---------------------------------------------------------------------------
// One term of the 256-term bilinear form. Template parameters guarantee
// compile-time indices (registers, not local memory) and a compile-time sign
// (folds into the FFMA negation modifier). The 256 instantiations are
// expanded FLAT via macros below — R5 showed linear template recursion blows
// nvcc's instantiation-depth cap, and R3 showed #pragma unroll on the nested
// loop silently fails (rolled loop + local-memory spill, 129us).
// ---------------------------------------------------------------------------

template <int I, int J>
__device__ __forceinline__ void do_term(const float (&A)[16],
                                        const float (&B)[16],
                                        float (&O)[16]) {
    constexpr float s = ct_sign(I, J);   // compile-time constant
    O[I ^ J] = fmaf(s * A[I], B[J], O[I ^ J]);
}

#define GP_T(I, J) do_term<(I), (J)>(A, B, O);
#define GP_ROW(I)                                                         \
    GP_T(I, 0)  GP_T(I, 1)  GP_T(I, 2)  GP_T(I, 3)                        \
    GP_T(I, 4)  GP_T(I, 5)  GP_T(I, 6)  GP_T(I, 7)                        \
    GP_T(I, 8)  GP_T(I, 9)  GP_T(I, 10) GP_T(I, 11)                       \
    GP_T(I, 12) GP_T(I, 13) GP_T(I, 14) GP_T(I, 15)

__device__ __forceinline__ void do_all(const float (&A)[16],
                                       const float (&B)[16],
                                       float (&O)[16]) {
    GP_ROW(0)  GP_ROW(1)  GP_ROW(2)  GP_ROW(3)
    GP_ROW(4)  GP_ROW(5)  GP_ROW(6)  GP_ROW(7)
    GP_ROW(8)  GP_ROW(9)  GP_ROW(10) GP_ROW(11)
    GP_ROW(12) GP_ROW(13) GP_ROW(14) GP_ROW(15)
}

__global__ void __launch_bounds__(256)
clifford_gp_kernel(const float4* __restrict__ a4,
                   const float4* __restrict__ b4,
                   float4* __restrict__ o4,
                   int n_rows) {
    int t = blockIdx.x * blockDim.x + threadIdx.x;
    if (t >= n_rows) return;

    float4 av0 = a4[t * 4 + 0];
    float4 av1 = a4[t * 4 + 1];
    float4 av2 = a4[t * 4 + 2];
    float4 av3 = a4[t * 4 + 3];
    float4 bv0 = b4[t * 4 + 0];
    float4 bv1 = b4[t * 4 + 1];
    float4 bv2 = b4[t * 4 + 2];
    float4 bv3 = b4[t * 4 + 3];

    float A[16] = {av0.x, av0.y, av0.z, av0.w,
                   av1.x, av1.y, av1.z, av1.w,
                   av2.x, av2.y, av2.z, av2.w,
                   av3.x, av3.y, av3.z, av3.w};
    float B[16] = {bv0.x, bv0.y, bv0.z, bv0.w,
                   bv1.x, bv1.y, bv1.z, bv1.w,
                   bv2.x, bv2.y, bv2.z, bv2.w,
                   bv3.x, bv3.y, bv3.z, bv3.w};

    float O[16] = {};

    do_all(A, B, O);

    // nan -> 0, then clip to [-1000, 1000] (covers the +-10000 inf mapping)
#pragma unroll
    for (int c = 0; c < 16; c++) {
        float v = O[c];
        if (v != v) v = 0.0f;
        v = fminf(fmaxf(v, -1000.0f), 1000.0f);
        O[c] = v;
    }

    o4[t * 4 + 0] = make_float4(O[0],  O[1],  O[2],  O[3]);
    o4[t * 4 + 1] = make_float4(O[4],  O[5],  O[6],  O[7]);
    o4[t * 4 + 2] = make_float4(O[8],  O[9],  O[10], O[11]);
    o4[t * 4 + 3] = make_float4(O[12], O[13], O[14], O[15]);
}

extern "C" void kernel_launch(void* const* d_in, const int* in_sizes, int n_in,
                              void* d_out, int out_size) {
    const float4* a4 = (const float4*)d_in[0];
    const float4* b4 = (const float4*)d_in[1];
    float4* o4 = (float4*)d_out;

    int n_rows = in_sizes[0] / 16;
    int threads = 256;
    int blocks = (n_rows + threads - 1) / threads;
    clifford_gp_kernel<<<blocks, threads>>>(a4, b4, o4, n_rows);
}